// round 7
// baseline (speedup 1.0000x reference)
#include <cuda_runtime.h>

#define DEC 256
#define FPSCALE 16777216.0f   // 2^24 fixed-point for deterministic integer accumulation

// Deterministic global accumulator (integer adds commute exactly) + ticket.
__device__ unsigned long long g_isum   = 0ULL;
__device__ int                g_counter = 0;

// Pad-swizzle: spreads the stride-4 (32B) lane pattern across banks.
__device__ __forceinline__ int swz(int j) { return j + (j >> 4); }

__device__ __forceinline__ unsigned long long pack2(float lo, float hi) {
    unsigned long long r;
    asm("mov.b64 %0, {%1, %2};" : "=l"(r) : "f"(lo), "f"(hi));
    return r;
}

__device__ __forceinline__ void pair_term(unsigned long long own,
                                          unsigned long long w, float& acc) {
    unsigned long long d;        // (o_i - o_j, t_i - t_j) in one packed add
    asm("add.rn.f32x2 %0, %1, %2;" : "=l"(d) : "l"(own), "l"(w));
    float dO, dt;
    asm("mov.b64 {%0, %1}, %2;" : "=f"(dO), "=f"(dt) : "l"(d));
    // x = sign(dt)*dO via one LOP3; dt==+-0 case has weight 0 so sign is moot.
    float x = __uint_as_float(__float_as_uint(dO) ^
                              (__float_as_uint(dt) & 0x80000000u));
    float h = fmaxf(x + 1.0f, 0.0f);
    if (fabsf(dt) > 0.1f) acc += h;
}

__global__ void __launch_bounds__(256)
rank_loss_fused(const float* __restrict__ inp, const float* __restrict__ tm,
                float* __restrict__ out, float scale) {
    __shared__ unsigned long long sh[544];   // negated (o,t), duplicated, padded
    __shared__ float warpsum[8];

    const int g    = blockIdx.x >> 1;   // group
    const int half = blockIdx.x & 1;    // k-tile: 0 -> k in [1..64], 1 -> [65..128]
    const int tid  = threadIdx.x;
    const int base = g * DEC;

    {
        float o = inp[base + tid];
        float t = tm[base + tid];
        unsigned long long nv = pack2(-o, -t);
        sh[swz(tid)]       = nv;
        sh[swz(tid + DEC)] = nv;
    }
    __syncthreads();

    // 4 k-subranges (16 each) x 64 row-quads.
    const int s   = tid >> 6;
    const int tau = tid & 63;
    const int b   = tau * 4;                 // first owned row
    const int k0  = half * 64 + s * 16 + 1;  // k in [k0, k0+15]

    unsigned long long own0 = pack2(inp[base + b + 0], tm[base + b + 0]);
    unsigned long long own1 = pack2(inp[base + b + 1], tm[base + b + 1]);
    unsigned long long own2 = pack2(inp[base + b + 2], tm[base + b + 2]);
    unsigned long long own3 = pack2(inp[base + b + 3], tm[base + b + 3]);

    unsigned long long w0 = sh[swz(b + k0 + 0)];
    unsigned long long w1 = sh[swz(b + k0 + 1)];
    unsigned long long w2 = sh[swz(b + k0 + 2)];
    unsigned long long w3 = sh[swz(b + k0 + 3)];

    float a0 = 0.0f, a1 = 0.0f, a2 = 0.0f, a3 = 0.0f;

    #pragma unroll
    for (int kk = 0; kk < 15; ++kk) {        // k = k0 .. k0+14, always active
        const int k = k0 + kk;
        pair_term(own0, w0, a0);
        pair_term(own1, w1, a1);
        pair_term(own2, w2, a2);
        pair_term(own3, w3, a3);
        w0 = w1; w1 = w2; w2 = w3;
        w3 = sh[swz(b + k + 4)];
    }
    // Epilogue k = k0+15. Only k=128 (half==1, s==3) is row<128 restricted,
    // i.e. inactive exactly when half==1 && tid >= 224.
    if (!(half && tid >= 224)) {
        pair_term(own0, w0, a0);
        pair_term(own1, w1, a1);
        pair_term(own2, w2, a2);
        pair_term(own3, w3, a3);
    }

    // Block reduction (fixed order).
    float ssum = (a0 + a1) + (a2 + a3);
    const int lane = tid & 31;
    const int w    = tid >> 5;
    #pragma unroll
    for (int off = 16; off; off >>= 1)
        ssum += __shfl_xor_sync(0xFFFFFFFFu, ssum, off);
    if (lane == 0) warpsum[w] = ssum;
    __syncthreads();

    if (tid == 0) {
        float bsum = 0.0f;
        #pragma unroll
        for (int j = 0; j < 8; ++j) bsum += warpsum[j];
        // Deterministic: fixed-point integer accumulation (order-independent).
        unsigned long long q = (unsigned long long)llrintf(bsum * FPSCALE);
        atomicAdd(&g_isum, q);
        __threadfence();
        int c = atomicAdd(&g_counter, 1);
        if (c == (int)gridDim.x - 1) {
            // All prior isum adds are fenced before their tickets -> visible.
            unsigned long long tot = atomicAdd(&g_isum, 0ULL);
            out[0] = (float)((double)tot * (1.0 / (double)FPSCALE) * (double)scale);
            g_isum    = 0ULL;     // reset for next graph replay
            __threadfence();
            g_counter = 0;
        }
    }
}

extern "C" void kernel_launch(void* const* d_in, const int* in_sizes, int n_in,
                              void* d_out, int out_size) {
    const float* inp = (const float*)d_in[0];   // input, [B,1] fp32
    const float* tm  = (const float*)d_in[1];   // gdt_ts, [B]  fp32

    const int B = in_sizes[0];
    const int K = B / DEC;
    const int G = K - 1;                        // reference skips the last group
    const double N = (double)G * DEC * (DEC - 1);
    const float scale = (float)(2.0 / N);       // x2: unordered -> ordered pairs

    rank_loss_fused<<<2 * G, 256>>>(inp, tm, (float*)d_out, scale);
}